// round 1
// baseline (speedup 1.0000x reference)
#include <cuda_runtime.h>

#define NFFT  4096
#define LOGN  12
#define NB    32
#define TLEN  4096
#define NF    128
#define NSERIES (NB*NF)          // 4096 series
#define NBINS 2049
#define KTOP  16
#define WIN   25
#define HALF  12
#define FFT_THREADS 512

// Scratch (static device globals; no allocation).
// g_xt: transposed input (B,F,T); reused as filtered xf by the inverse kernel.
__device__ float  g_xt[(size_t)NSERIES * TLEN];
__device__ float2 g_tw[NFFT/2];
__device__ int    g_topk_idx[NSERIES * KTOP];
__device__ float2 g_topk_val[NSERIES * KTOP];

// ---------------------------------------------------------------- twiddles
__global__ void init_tw_kernel() {
    int k = blockIdx.x * blockDim.x + threadIdx.x;
    if (k < NFFT/2) {
        double a = -2.0 * (double)k / (double)NFFT;   // units of pi
        g_tw[k] = make_float2((float)cospi(a), (float)sinpi(a));
    }
}

// ---------------------------------------------------------------- transpose (B,T,F) -> (B,F,T)
__global__ void __launch_bounds__(256) transpose_kernel(const float* __restrict__ x) {
    __shared__ float tile[32][33];
    int b  = blockIdx.z;
    int t0 = blockIdx.x * 32;
    int f0 = blockIdx.y * 32;
    int tx = threadIdx.x, ty = threadIdx.y;   // (32, 8)
    #pragma unroll
    for (int i = 0; i < 4; i++) {
        int t = t0 + ty + i*8;
        tile[ty + i*8][tx] = x[((size_t)b*TLEN + t)*NF + (f0 + tx)];
    }
    __syncthreads();
    #pragma unroll
    for (int i = 0; i < 4; i++) {
        int f = f0 + ty + i*8;
        g_xt[((size_t)(b*NF + f))*TLEN + (t0 + tx)] = tile[tx][ty + i*8];
    }
}

// ---------------------------------------------------------------- Stockham radix-2 in smem
// Forward DFT for tsign=+1 (twiddles e^{-2pi i k/N}); set tsign=-1 for unnormalized inverse.
// 12 stages (even) -> result ends in buf0.
__device__ __forceinline__ void fft_smem(float2* buf0, float2* buf1, int tid, float tsign) {
    float2* cur = buf0;
    float2* oth = buf1;
    #pragma unroll 1
    for (int s = 0; s < LOGN; s++) {
        int m = 1 << s;
        #pragma unroll
        for (int u = 0; u < (NFFT/2)/FFT_THREADS; u++) {
            int i  = tid + u*FFT_THREADS;          // butterfly id, 0..2047
            int jm = i & ~(m - 1);                 // j*m
            float2 c0 = cur[i];
            float2 c1 = cur[i + NFFT/2];
            float2 w  = g_tw[jm];
            w.y *= tsign;
            float2 su = make_float2(c0.x + c1.x, c0.y + c1.y);
            float2 df = make_float2(c0.x - c1.x, c0.y - c1.y);
            float2 wd = make_float2(w.x*df.x - w.y*df.y, w.x*df.y + w.y*df.x);
            oth[i + jm]     = su;                  // k + 2*j*m
            oth[i + jm + m] = wd;
        }
        __syncthreads();
        float2* t2 = cur; cur = oth; oth = t2;
    }
}

// ---------------------------------------------------------------- forward FFT + top-k
// One CTA per pair of series (packed real FFT: z = a + i*b).
__global__ void __launch_bounds__(FFT_THREADS) fwd_kernel() {
    extern __shared__ float2 smbuf[];
    float2* buf0 = smbuf;
    float2* buf1 = smbuf + NFFT;
    __shared__ float red_v[16];
    __shared__ int   red_i[16];

    int pair = blockIdx.x;
    int sa   = pair * 2;
    int tid  = threadIdx.x;
    const float* rowa = g_xt + (size_t)sa * TLEN;
    const float* rowb = rowa + TLEN;

    for (int t = tid; t < NFFT; t += FFT_THREADS)
        buf0[t] = make_float2(rowa[t], rowb[t]);
    __syncthreads();

    fft_smem(buf0, buf1, tid, 1.0f);   // result (Z) in buf0; buf1 free

    // magnitudes^2 of both unpacked spectra, stored in buf1's space
    float* magA = (float*)buf1;        // 2049 floats
    float* magB = magA + 2064;         // 2049 floats (padded offset)
    for (int m = tid; m < NBINS; m += FFT_THREADS) {
        float2 z  = buf0[m];
        float2 zm = buf0[(NFFT - m) & (NFFT - 1)];
        float ar = 0.5f*(z.x + zm.x), ai = 0.5f*(z.y - zm.y);   // A[m]
        float br = 0.5f*(z.y + zm.y), bi = 0.5f*(zm.x - z.x);   // B[m]
        magA[m] = ar*ar + ai*ai;
        magB[m] = br*br + bi*bi;
    }
    __syncthreads();

    // top-16 per series via 16 argmax passes (ties -> lower index, matching lax.top_k)
    for (int srs = 0; srs < 2; srs++) {
        float* mag = srs ? magB : magA;
        int sid = sa + srs;
        for (int it = 0; it < KTOP; it++) {
            float bv = -1.0f; int bi2 = NBINS;
            for (int m = tid; m < NBINS; m += FFT_THREADS) {
                float v = mag[m];
                if (v > bv) { bv = v; bi2 = m; }
            }
            #pragma unroll
            for (int off = 16; off; off >>= 1) {
                float ov = __shfl_down_sync(0xffffffffu, bv, off);
                int   oi = __shfl_down_sync(0xffffffffu, bi2, off);
                if (ov > bv || (ov == bv && oi < bi2)) { bv = ov; bi2 = oi; }
            }
            if ((tid & 31) == 0) { red_v[tid >> 5] = bv; red_i[tid >> 5] = bi2; }
            __syncthreads();
            if (tid == 0) {
                float bbv = red_v[0]; int bbi = red_i[0];
                #pragma unroll
                for (int wg = 1; wg < 16; wg++) {
                    if (red_v[wg] > bbv || (red_v[wg] == bbv && red_i[wg] < bbi)) {
                        bbv = red_v[wg]; bbi = red_i[wg];
                    }
                }
                mag[bbi] = -2.0f;                     // remove for next pass
                int m = bbi;
                float2 z  = buf0[m];
                float2 zm = buf0[(NFFT - m) & (NFFT - 1)];
                float2 val = (srs == 0)
                    ? make_float2(0.5f*(z.x + zm.x), 0.5f*(z.y - zm.y))
                    : make_float2(0.5f*(z.y + zm.y), 0.5f*(zm.x - z.x));
                g_topk_idx[sid*KTOP + it] = m;
                g_topk_val[sid*KTOP + it] = val;
            }
            __syncthreads();
        }
    }
}

// ---------------------------------------------------------------- sparse inverse FFT
// One CTA per pair; build Z = Ya + i*Yb from the 2x16 kept bins, iFFT, write xf into g_xt.
__global__ void __launch_bounds__(FFT_THREADS) inv_kernel() {
    extern __shared__ float2 smbuf[];
    float2* buf0 = smbuf;
    float2* buf1 = smbuf + NFFT;
    int pair = blockIdx.x;
    int sa   = pair * 2;
    int tid  = threadIdx.x;

    for (int t = tid; t < NFFT; t += FFT_THREADS)
        buf0[t] = make_float2(0.f, 0.f);
    __syncthreads();

    if (tid == 0) {
        // series a: Y[m] += V ; Y[N-m] += conj(V) for 0<m<N/2
        #pragma unroll 1
        for (int it = 0; it < KTOP; it++) {
            int m = g_topk_idx[sa*KTOP + it];
            float2 v = g_topk_val[sa*KTOP + it];
            buf0[m].x += v.x; buf0[m].y += v.y;
            if (m != 0 && m != NFFT/2) {
                buf0[NFFT - m].x += v.x; buf0[NFFT - m].y -= v.y;
            }
        }
        // series b: Y[m] += i*V = (-vy, vx) ; Y[N-m] += i*conj(V) = (vy, vx)
        #pragma unroll 1
        for (int it = 0; it < KTOP; it++) {
            int m = g_topk_idx[(sa+1)*KTOP + it];
            float2 v = g_topk_val[(sa+1)*KTOP + it];
            buf0[m].x += -v.y; buf0[m].y += v.x;
            if (m != 0 && m != NFFT/2) {
                buf0[NFFT - m].x += v.y; buf0[NFFT - m].y += v.x;
            }
        }
    }
    __syncthreads();

    fft_smem(buf0, buf1, tid, -1.0f);  // unnormalized inverse, result in buf0

    float* rowa = g_xt + (size_t)sa * TLEN;
    float* rowb = rowa + TLEN;
    const float scale = 1.0f / (float)NFFT;
    for (int t = tid; t < NFFT; t += FFT_THREADS) {
        float2 z = buf0[t];
        rowa[t] = z.x * scale;   // Re -> series a
        rowb[t] = z.y * scale;   // Im -> series b
    }
}

// ---------------------------------------------------------------- smoothing + transpose back
// Tile: 32 features x 128 time. Symmetric flip padding at global edges.
__global__ void __launch_bounds__(256) smooth_kernel(float* __restrict__ out) {
    __shared__ float sin_[32][153];    // 128+24 cols, row stride 153 (odd -> conflict-free)
    __shared__ float sout[128][33];
    __shared__ float swt[WIN];
    int b  = blockIdx.z;
    int f0 = blockIdx.y * 32;
    int t0 = blockIdx.x * 128;
    int tid = threadIdx.x;

    if (tid < WIN)
        swt[tid] = (0.54f - 0.46f * cospif(2.0f * (float)tid / (float)WIN)) * (1.0f / 13.5f);

    for (int idx = tid; idx < 32 * 152; idx += 256) {
        int r = idx / 152;
        int c = idx - r * 152;
        int gt = t0 + c - HALF;
        if (gt < 0)          gt = -1 - gt;          // left flip:  x[-1-i]
        else if (gt >= TLEN) gt = 2*TLEN - 1 - gt;  // right flip: x[2T-1-i]
        sin_[r][c] = g_xt[((size_t)(b*NF + f0 + r))*TLEN + gt];
    }
    __syncthreads();

    float wr[WIN];
    #pragma unroll
    for (int n = 0; n < WIN; n++) wr[n] = swt[n];

    int f  = tid & 31;
    int g  = tid >> 5;        // 0..7, each handles 16 consecutive outputs
    int c0 = g * 16;
    float v[16 + WIN - 1];
    #pragma unroll
    for (int j = 0; j < 16 + WIN - 1; j++) v[j] = sin_[f][c0 + j];
    #pragma unroll
    for (int o = 0; o < 16; o++) {
        float a = 0.f;
        #pragma unroll
        for (int n = 0; n < WIN; n++) a = fmaf(wr[n], v[o + n], a);
        sout[c0 + o][f] = a;
    }
    __syncthreads();

    for (int idx = tid; idx < 128 * 32; idx += 256) {
        int tt = idx >> 5, ff = idx & 31;
        out[((size_t)b*TLEN + (t0 + tt))*NF + (f0 + ff)] = sout[tt][ff];
    }
}

// ---------------------------------------------------------------- launch
extern "C" void kernel_launch(void* const* d_in, const int* in_sizes, int n_in,
                              void* d_out, int out_size) {
    const float* x = (const float*)d_in[0];
    float* out = (float*)d_out;
    // window_size=25, k=16 are fixed problem constants (compiled in).

    size_t fft_smem_bytes = 2 * NFFT * sizeof(float2);   // 64 KB
    cudaFuncSetAttribute(fwd_kernel, cudaFuncAttributeMaxDynamicSharedMemorySize, (int)fft_smem_bytes);
    cudaFuncSetAttribute(inv_kernel, cudaFuncAttributeMaxDynamicSharedMemorySize, (int)fft_smem_bytes);

    init_tw_kernel<<<(NFFT/2 + 255)/256, 256>>>();
    transpose_kernel<<<dim3(TLEN/32, NF/32, NB), dim3(32, 8)>>>(x);
    fwd_kernel<<<NSERIES/2, FFT_THREADS, fft_smem_bytes>>>();
    inv_kernel<<<NSERIES/2, FFT_THREADS, fft_smem_bytes>>>();
    smooth_kernel<<<dim3(TLEN/128, NF/32, NB), 256>>>(out);
}